// round 10
// baseline (speedup 1.0000x reference)
#include <cuda_runtime.h>
#include <math.h>

// DPSR: scatter -> 3D rFFT -> spectral Poisson solve -> 3D irFFT -> gather/normalize
// Fused pipeline (3 FFT kernels) + spectral cutoff propagated end-to-end:
//   G = exp(-0.0122*d2) < 1.1e-8 for fy^2+fz^2 > 1500 at any kx -> those (ky,kz)
//   lines contribute ~0. K1 skips their stores, K2 never sees them (grid cut to
//   kz<39 + per-line skip + predicated stores), K3 zero-fills them on load.
//
// Axis conventions:
//   - ky axis of d_sp/d_inv1 DIGIT-REVERSED: address a holds frequency
//     f = 4*bitrev5(a&31) + (a>>5). Writers store lane t reg r at a=t+32r.
//   - z axis of d_phi digit-reversed the same way; gather/final permute addresses.
//   - kz truncated natural (0..64); x, y natural.

#define NRES 128
#define NKZ  65
#define VOL  (NRES*NRES*NRES)
#define NPTS 65536
#define K2L  8           // kya lines per K2 block
#define K2P  9           // K2 tile pad stride
#define K2TS (128*K2P)   // padded tile size (float2) per channel
#define K1PD 129         // K1 stage-1 smem row stride (float2), odd
#define CUT2 1500.0f     // skip line if fy^2+fz^2 > CUT2  (G < 1.1e-8)
#define KZCUT 39         // kz >= KZCUT -> fz^2 > CUT2 for all ky

__device__ float  d_ras[6*VOL];                 // [bc][x][y][z]
__device__ float2 d_sp[6*NRES*NKZ*NRES];        // [bc][x][kz][kya]
__device__ float2 d_inv1[2*NKZ*NRES*NRES];      // [b][kz][x][kya]
__device__ float  d_phi[2*VOL];                 // [b][x][y][za]
__device__ float  d_accum[2];

__device__ __forceinline__ float2 cmul(float2 a, float2 b) {
    return make_float2(a.x*b.x - a.y*b.y, a.x*b.y + a.y*b.x);
}
__device__ __forceinline__ float2 cadd(float2 a, float2 b) { return make_float2(a.x+b.x, a.y+b.y); }
__device__ __forceinline__ float2 csub(float2 a, float2 b) { return make_float2(a.x-b.x, a.y-b.y); }
__device__ __forceinline__ int bitrev5(int t) { return (int)(__brev((unsigned)t) >> 27); }
__device__ __forceinline__ int paddr(int k) { return bitrev5(k >> 2) + ((k & 3) << 5); }
__device__ __forceinline__ float freq_of(int fyi) {
    return (fyi < 64) ? (float)fyi : (float)(fyi - 128);
}

__device__ __forceinline__ void build_tw64(float2* tw, int tid, float sign) {
    if (tid < 64) {
        float s, c;
        sincosf(sign * 6.28318530717958647f * (float)tid * (1.0f/128.0f), &s, &c);
        tw[tid] = make_float2(c, s);
    }
}

// Natural-input warp FFT. Lane t holds v[r]=x[t+32r]; out v[r]=X[4*bitrev5(t)+r].
template<int DIR>
__device__ __forceinline__ void warp_fft128(float2 v[4], const float2* __restrict__ tw, int t) {
    float2 t0 = cadd(v[0], v[2]);
    float2 t1 = csub(v[0], v[2]);
    float2 t2 = cadd(v[1], v[3]);
    float2 t3 = csub(v[1], v[3]);
    float2 t3r = DIR ? make_float2(-t3.y, t3.x) : make_float2(t3.y, -t3.x);
    v[0] = cadd(t0, t2);
    v[2] = csub(t0, t2);
    v[1] = cadd(t1, t3r);
    v[3] = csub(t1, t3r);
    float2 w1 = tw[t], w2 = tw[2*t];
    v[1] = cmul(v[1], w1);
    v[2] = cmul(v[2], w2);
    v[3] = cmul(v[3], cmul(w1, w2));
#pragma unroll
    for (int d = 16; d >= 1; d >>= 1) {
        int m = (t & (d-1)) * (16/d);
        float2 w = tw[4*m];
        bool hi = (t & d) != 0;
        float s = hi ? -1.f : 1.f;
#pragma unroll
        for (int r = 0; r < 4; r++) {
            float2 p;
            p.x = __shfl_xor_sync(0xffffffffu, v[r].x, d);
            p.y = __shfl_xor_sync(0xffffffffu, v[r].y, d);
            float2 tmp = make_float2(p.x + s*v[r].x, p.y + s*v[r].y);
            v[r] = hi ? cmul(tmp, w) : tmp;
        }
    }
}

// Mirror-DIT inverse: consumes digit-reversed layout, produces natural order.
__device__ __forceinline__ void warp_ifft128_rev(float2 v[4], const float2* __restrict__ twp, int t) {
#pragma unroll
    for (int d = 1; d <= 16; d <<= 1) {
        int m = (t & (d-1)) * (16/d);
        float2 w = twp[4*m];
        bool hi = (t & d) != 0;
#pragma unroll
        for (int r = 0; r < 4; r++) {
            float2 u = hi ? cmul(v[r], w) : v[r];
            float2 p;
            p.x = __shfl_xor_sync(0xffffffffu, u.x, d);
            p.y = __shfl_xor_sync(0xffffffffu, u.y, d);
            v[r] = hi ? csub(p, u) : cadd(u, p);
        }
    }
    float2 w1 = twp[t], w2 = twp[2*t];
    v[1] = cmul(v[1], w1);
    v[2] = cmul(v[2], w2);
    v[3] = cmul(v[3], cmul(w1, w2));
    float2 t0 = cadd(v[0], v[2]), t1 = csub(v[0], v[2]);
    float2 t2 = cadd(v[1], v[3]), t3 = csub(v[1], v[3]);
    float2 t3r = make_float2(-t3.y, t3.x);
    v[0] = cadd(t0, t2);
    v[1] = cadd(t1, t3r);
    v[2] = csub(t0, t2);
    v[3] = csub(t1, t3r);
}

// ---------------------------------------------------------------- zero scratch
__global__ void k_zero() {
    int i = blockIdx.x * blockDim.x + threadIdx.x;
    float4* p = (float4*)d_ras;
    int n4 = 6*VOL/4;
    for (int k = i; k < n4; k += gridDim.x * blockDim.x)
        p[k] = make_float4(0.f, 0.f, 0.f, 0.f);
    if (i < 2) d_accum[i] = 0.f;
}

// ---------------------------------------------------------------- scatter
__global__ void k_scatter(const float* __restrict__ V, const float* __restrict__ N) {
    int id = blockIdx.x * blockDim.x + threadIdx.x;
    if (id >= 2*NPTS) return;
    int b = id >> 16;
    float px = V[3*id+0]*128.f, py = V[3*id+1]*128.f, pz = V[3*id+2]*128.f;
    int ix0 = max(0, min(127, (int)floorf(px)));
    int iy0 = max(0, min(127, (int)floorf(py)));
    int iz0 = max(0, min(127, (int)floorf(pz)));
    float fx = px - (float)ix0, fy = py - (float)iy0, fz = pz - (float)iz0;
    int ix[2] = {ix0, (ix0+1)&127};
    int iy[2] = {iy0, (iy0+1)&127};
    int iz[2] = {iz0, (iz0+1)&127};
    float wx[2] = {1.f-fx, fx}, wy[2] = {1.f-fy, fy}, wz[2] = {1.f-fz, fz};
    float nx = N[3*id+0], ny = N[3*id+1], nz = N[3*id+2];
    float* r = d_ras + (size_t)b*3*VOL;
#pragma unroll
    for (int cx = 0; cx < 2; cx++)
#pragma unroll
        for (int cy = 0; cy < 2; cy++)
#pragma unroll
            for (int cz = 0; cz < 2; cz++) {
                int sp = (ix[cx]*NRES + iy[cy])*NRES + iz[cz];
                float w = wx[cx]*wy[cy]*wz[cz];
                atomicAdd(r + sp,          w*nx);
                atomicAdd(r + VOL + sp,    w*ny);
                atomicAdd(r + 2*VOL + sp,  w*nz);
            }
}

// --------------- K1: packed-pair real z-FFTs + Hermitian split + y-FFT
__global__ void __launch_bounds__(512, 3) k_fwdZY() {
    extern __shared__ float2 sh[];              // 64 * K1PD float2
    __shared__ float2 tw[64];
    int tid = threadIdx.x, w = tid >> 5, t = tid & 31;
    build_tw64(tw, tid, -1.f);
    __syncthreads();
    int x = blockIdx.x, bc = blockIdx.y;
    const float* base = d_ras + (size_t)(bc*NRES + x) * NRES * NRES;
    // stage 1: 64 packed pairs (y=2m, 2m+1) -> one complex FFT each
    for (int j = 0; j < 4; j++) {
        int m = w + 16*j;
        const float* inA = base + (2*m)*NRES;
        const float* inB = inA + NRES;
        float2 v[4];
#pragma unroll
        for (int r = 0; r < 4; r++) v[r] = make_float2(inA[t + 32*r], inB[t + 32*r]);
        warp_fft128<0>(v, tw, t);
#pragma unroll
        for (int r = 0; r < 4; r++) sh[m*K1PD + t + 32*r] = v[r];   // permuted kz, cf
    }
    __syncthreads();
    // stage 2: y-lines for kz < KZCUT only; stores predicated on ky cutoff
    float2* dstp = d_sp + (size_t)(bc*NRES + x) * NKZ * NRES;
    int half = t >> 1;
    bool odd = (t & 1) != 0;
    int u = bitrev5(t);
    for (int kz = w; kz < KZCUT; kz += 16) {
        int a1 = paddr(kz);
        int a2 = paddr((128 - kz) & 127);
        float fz2 = (float)(kz*kz);
        float2 v[4];
#pragma unroll
        for (int r = 0; r < 4; r++) {
            int m = half + 16*r;                 // y = t+32r, m = y>>1, parity = t&1
            float2 P1 = sh[m*K1PD + a1];
            float2 P2 = sh[m*K1PD + a2];
            if (!odd) v[r] = make_float2(0.5f*(P1.x + P2.x), 0.5f*(P1.y - P2.y));
            else      v[r] = make_float2(0.5f*(P1.y + P2.y), 0.5f*(P2.x - P1.x));
        }
        warp_fft128<0>(v, tw, t);
        float2* dst = dstp + kz*NRES;
#pragma unroll
        for (int r = 0; r < 4; r++) {
            float fy = freq_of(4*u + r);         // freq at address t+32r
            if (fy*fy + fz2 <= CUT2) dst[t + 32*r] = v[r];
        }
    }
}

// ------------- K2: per-line cutoff; sequential fwd X/YZ FFTs + combine + inverse
// Grid y covers only kz < KZCUT. Cut lines: no load, no FFT, no store.
__global__ void __launch_bounds__(256, 5) k_specX() {
    extern __shared__ float2 tile[];            // 2 * K2TS float2 (18 KB)
    __shared__ float2 twf[64];
    __shared__ float2 twi[64];
    int tid = threadIdx.x, l = tid >> 5, t = tid & 31;
    build_tw64(twf, tid, -1.f);
    if (tid >= 64 && tid < 128) build_tw64(twi, tid - 64, 1.f);
    int c = blockIdx.x, kz = blockIdx.y, b = blockIdx.z;
    int kya0 = K2L*c;
    const float TWOPI = 6.28318530717958647f;
    float fz = (float)kz;
    float fz2 = fz*fz;
    float2* tileX  = tile;
    float2* tileYZ = tile + K2TS;
    // ---- load phase: only non-cut lines (ch0 raw; ch1,ch2 combined)
    {
        const float2* src0 = d_sp + ((size_t)(b*3 + 0)*NRES*NKZ + kz)*NRES + kya0;
        const float2* src1 = src0 + (size_t)NRES*NKZ*NRES;
        const float2* src2 = src1 + (size_t)NRES*NKZ*NRES;
        for (int i = tid; i < 128*K2L; i += 256) {
            int xx = i >> 3, kyl = i & 7;
            int kya = kya0 + kyl;
            float fy = freq_of(4*bitrev5(kya & 31) + (kya >> 5));
            if (fy*fy + fz2 > CUT2) continue;          // cut line: no load
            size_t off = (size_t)xx*NKZ*NRES + kyl;
            float2 e1 = src1[off];
            float2 e2 = src2[off];
            tileX[xx*K2P + kyl] = src0[off];
            tileYZ[xx*K2P + kyl] = make_float2(TWOPI*(fy*e1.x + fz*e2.x),
                                               TWOPI*(fy*e1.y + fz*e2.y));
        }
    }
    __syncthreads();
    int kya = kya0 + l;
    int fyi = 4*bitrev5(kya & 31) + (kya >> 5);
    float fy = freq_of(fyi);
    int u = bitrev5(t);
    if (fy*fy + fz2 <= CUT2) {
        // fwd FFT of X channel; park spectrum in own column
        {
            float2 vX[4];
#pragma unroll
            for (int r = 0; r < 4; r++) vX[r] = tileX[(t + 32*r)*K2P + l];
            warp_fft128<0>(vX, twf, t);
#pragma unroll
            for (int r = 0; r < 4; r++) tileX[(t + 32*r)*K2P + l] = vX[r];
        }
        // fwd FFT of YZ channel, then combine with parked X spectrum
        float2 v[4];
#pragma unroll
        for (int r = 0; r < 4; r++) v[r] = tileYZ[(t + 32*r)*K2P + l];
        warp_fft128<0>(v, twf, t);
#pragma unroll
        for (int r = 0; r < 4; r++) {
            float2 xs = tileX[(t + 32*r)*K2P + l];
            int kx = 4*u + r;
            float fx = (float)(kx < 64 ? kx : kx - 128);
            float wx = TWOPI * fx;
            float2 acc = make_float2(wx*xs.x + v[r].x, wx*xs.y + v[r].y);
            float d2 = fx*fx + fy*fy + fz2;
            float G = expf(-0.01220703125f * d2);            // 0.5*(sig*2/128)^2
            float L = -39.478417604357434f * d2 + 1e-6f;     // -4*pi^2*|f|^2 + eps
            v[r] = make_float2(G*acc.y/L, -G*acc.x/L);       // -i*G*acc/L
            if (kx == 0 && fyi == 0 && kz == 0) v[r] = make_float2(0.f, 0.f);
        }
        warp_ifft128_rev(v, twi, t);            // -> natural x order
#pragma unroll
        for (int r = 0; r < 4; r++) tileX[(t + 32*r)*K2P + l] = v[r];
    }
    __syncthreads();
    // store only kept columns (K3 zero-fills the cut ones)
    float2* dst = d_inv1 + (size_t)(b*NKZ + kz)*NRES*NRES + kya0;
    for (int i = tid; i < 128*K2L; i += 256) {
        int xx = i >> 3, kyl = i & 7;
        int kya2 = kya0 + kyl;
        float fyw = freq_of(4*bitrev5(kya2 & 31) + (kya2 >> 5));
        if (fyw*fyw + fz2 > CUT2) continue;
        dst[(size_t)xx*NRES + kyl] = tileX[xx*K2P + kyl];
    }
}

// --------------- K3: inverse y-FFT (mirror-DIT) + packed-pair C2R z-FFTs
__global__ void __launch_bounds__(512, 3) k_invYZ() {
    extern __shared__ float2 sh[];              // 128*65 float2 : sh[y][kz]
    __shared__ float2 twi[64];
    int tid = threadIdx.x, w = tid >> 5, t = tid & 31;
    build_tw64(twi, tid, 1.f);
    __syncthreads();
    int x = blockIdx.x, b = blockIdx.y;
    int u = bitrev5(t);
    // stage 1: ky-lines; cut elements (per-address cutoff) read as zero
    for (int kz = w; kz < NKZ; kz += 16) {
        if (kz < KZCUT) {
            float fz2 = (float)(kz*kz);
            const float2* in = d_inv1 + ((size_t)(b*NKZ + kz)*NRES + x)*NRES;
            float2 v[4];
#pragma unroll
            for (int r = 0; r < 4; r++) {
                float fy = freq_of(4*u + r);     // freq at address t+32r
                v[r] = (fy*fy + fz2 <= CUT2) ? in[t + 32*r] : make_float2(0.f, 0.f);
            }
            warp_ifft128_rev(v, twi, t);        // natural y = t+32r
#pragma unroll
            for (int r = 0; r < 4; r++) sh[(t + 32*r)*NKZ + kz] = v[r];
        } else {
            float2 z0 = make_float2(0.f, 0.f);
#pragma unroll
            for (int r = 0; r < 4; r++) sh[(t + 32*r)*NKZ + kz] = z0;
        }
    }
    __syncthreads();
    // stage 2: 64 packed C2R pairs: G = S_{2m} + i*S_{2m+1}, one inverse FFT
    const float sc = 1.0f / 2097152.0f;         // 1/128^3
    float* outb = d_phi + (size_t)(b*NRES + x) * NRES * NRES;
    for (int j = 0; j < 4; j++) {
        int m = w + 16*j;
        const float2* rowA = sh + (2*m)*NKZ;
        const float2* rowB = rowA + NKZ;
        float2 v[4];
#pragma unroll
        for (int r = 0; r < 4; r++) {
            int k = t + 32*r;
            if (k <= 64) {
                float2 A = rowA[k], B = rowB[k];
                v[r] = make_float2(A.x - B.y, A.y + B.x);
            } else {
                int k2 = 128 - k;
                float2 A = rowA[k2], B = rowB[k2];
                v[r] = make_float2(A.x + B.y, B.x - A.y);
            }
        }
        warp_fft128<1>(v, twi, t);
        float* oA = outb + (2*m)*NRES;
        float* oB = oA + NRES;
#pragma unroll
        for (int r = 0; r < 4; r++) {
            oA[t + 32*r] = v[r].x * sc;         // y=2m,   permuted z
            oB[t + 32*r] = v[r].y * sc;         // y=2m+1, permuted z
        }
    }
}

// ---------------------------------------------------------------- gather + mean
__global__ void k_gather(const float* __restrict__ V) {
    __shared__ float red[256];
    int id = blockIdx.x * 256 + threadIdx.x;    // 131072; b uniform per block
    int b = id >> 16;
    float px = V[3*id+0]*128.f, py = V[3*id+1]*128.f, pz = V[3*id+2]*128.f;
    int ix0 = max(0, min(127, (int)floorf(px)));
    int iy0 = max(0, min(127, (int)floorf(py)));
    int iz0 = max(0, min(127, (int)floorf(pz)));
    float fx = px - (float)ix0, fy = py - (float)iy0, fz = pz - (float)iz0;
    int ix[2] = {ix0, (ix0+1)&127};
    int iy[2] = {iy0, (iy0+1)&127};
    int az[2] = {paddr(iz0), paddr((iz0+1)&127)};
    float wx[2] = {1.f-fx, fx}, wy[2] = {1.f-fy, fy}, wz[2] = {1.f-fz, fz};
    const float* ph = d_phi + (size_t)b*VOL;
    float fv = 0.f;
#pragma unroll
    for (int cx = 0; cx < 2; cx++)
#pragma unroll
        for (int cy = 0; cy < 2; cy++)
#pragma unroll
            for (int cz = 0; cz < 2; cz++)
                fv += wx[cx]*wy[cy]*wz[cz] * ph[(ix[cx]*NRES + iy[cy])*NRES + az[cz]];
    red[threadIdx.x] = fv;
    __syncthreads();
    for (int s = 128; s > 0; s >>= 1) {
        if (threadIdx.x < s) red[threadIdx.x] += red[threadIdx.x + s];
        __syncthreads();
    }
    if (threadIdx.x == 0) atomicAdd(&d_accum[b], red[0]);
}

// ---------------------------------------------------------------- finalize
__global__ void k_final(float* __restrict__ out) {
    int id = blockIdx.x * 256 + threadIdx.x;    // 4194304 total
    int b = id >> 21;
    int z = id & 127;
    int base = id - z;
    float off  = d_accum[b] * (1.0f/65536.0f);
    float p000 = d_phi[(size_t)b * VOL];        // paddr(0)=0
    float s = 0.5f / fabsf(p000 - off);
    out[id] = -(d_phi[base + paddr(z)] - off) * s;
}

// ---------------------------------------------------------------- launch
extern "C" void kernel_launch(void* const* d_in, const int* in_sizes, int n_in,
                              void* d_out, int out_size) {
    const float* V = (const float*)d_in[0];
    const float* N = (const float*)d_in[1];
    float* out = (float*)d_out;

    const int k1Bytes = 64*K1PD*sizeof(float2);       // 66048
    const int k3Bytes = NRES*NKZ*sizeof(float2);      // 66560
    const int k2Bytes = 2*K2TS*sizeof(float2);        // 18432
    cudaFuncSetAttribute(k_fwdZY, cudaFuncAttributeMaxDynamicSharedMemorySize, k1Bytes);
    cudaFuncSetAttribute(k_invYZ, cudaFuncAttributeMaxDynamicSharedMemorySize, k3Bytes);

    k_zero<<<4096, 256>>>();
    k_scatter<<<512, 256>>>(V, N);
    k_fwdZY<<<dim3(128, 6), 512, k1Bytes>>>();        // 768 planes
    k_specX<<<dim3(16, KZCUT, 2), 256, k2Bytes>>>();  // only kz < 39
    k_invYZ<<<dim3(128, 2), 512, k3Bytes>>>();        // 256 planes
    k_gather<<<512, 256>>>(V);
    k_final<<<16384, 256>>>(out);
}

// round 12
// speedup vs baseline: 1.1161x; 1.1161x over previous
#include <cuda_runtime.h>
#include <math.h>

// DPSR: scatter -> 3D rFFT -> spectral Poisson solve -> 3D irFFT -> gather/normalize
// Fused pipeline (3 FFT kernels) + spectral cutoff propagated end-to-end:
//   G = exp(-0.0122*d2) < 5e-6 for fy^2+fz^2 > 1000 at any kx -> those (ky,kz)
//   lines contribute negligibly. K1 skips their stores, K2 never sees them,
//   K3 zero-fills them on load.
//
// Axis conventions:
//   - ky axis of d_sp/d_inv1 DIGIT-REVERSED: address a holds frequency
//     f = 4*bitrev5(a&31) + (a>>5). Writers store lane t reg r at a=t+32r.
//   - z axis of d_ras 4-PERMUTED (pz4): address 4t+r holds z = t+32r ->
//     lane t float4 load yields the FFT input convention directly.
//   - z axis of d_phi FFT-OUTPUT-PERMUTED (pphi): address 4t+r holds
//     z = 4*bitrev5(t)+r (what warp_fft128's digit-reversed output produces
//     under a float4 store). pphi(z) = (bitrev5(z>>2)<<2) | (z&3); pphi(0)=0.
//   - kz truncated natural (0..64); x, y natural.

#define NRES 128
#define NKZ  65
#define VOL  (NRES*NRES*NRES)
#define NPTS 65536
#define K2L  8           // kya lines per K2 block
#define K2P  9           // K2 tile pad stride
#define K2TS (128*K2P)   // padded tile size (float2) per channel
#define K1PD 129         // K1 stage-1 smem row stride (float2), odd
#define CUT2 1000.0f     // skip line if fy^2+fz^2 > CUT2  (G < 5e-6)
#define KZCUT 32         // kz >= KZCUT -> fz^2 > CUT2 for all ky

__device__ __align__(16) float  d_ras[6*VOL];   // [bc][x][y][za4]
__device__ float2 d_sp[6*NRES*NKZ*NRES];        // [bc][x][kz][kya]
__device__ float2 d_inv1[2*NKZ*NRES*NRES];      // [b][kz][x][kya]
__device__ __align__(16) float  d_phi[2*VOL];   // [b][x][y][z-pphi]
__device__ float  d_accum[2];

__device__ __forceinline__ float2 cmul(float2 a, float2 b) {
    return make_float2(a.x*b.x - a.y*b.y, a.x*b.y + a.y*b.x);
}
__device__ __forceinline__ float2 cadd(float2 a, float2 b) { return make_float2(a.x+b.x, a.y+b.y); }
__device__ __forceinline__ float2 csub(float2 a, float2 b) { return make_float2(a.x-b.x, a.y-b.y); }
__device__ __forceinline__ int bitrev5(int t) { return (int)(__brev((unsigned)t) >> 27); }
__device__ __forceinline__ int paddr(int k) { return bitrev5(k >> 2) + ((k & 3) << 5); }
__device__ __forceinline__ int pz4(int z) { return ((z & 31) << 2) | (z >> 5); }
__device__ __forceinline__ int pphi(int z) { return (bitrev5(z >> 2) << 2) | (z & 3); }
__device__ __forceinline__ float freq_of(int fyi) {
    return (fyi < 64) ? (float)fyi : (float)(fyi - 128);
}

__device__ __forceinline__ void build_tw64(float2* tw, int tid, float sign) {
    if (tid < 64) {
        float s, c;
        sincosf(sign * 6.28318530717958647f * (float)tid * (1.0f/128.0f), &s, &c);
        tw[tid] = make_float2(c, s);
    }
}

// Natural-input warp FFT. Lane t holds v[r]=x[t+32r]; out v[r]=X[4*bitrev5(t)+r].
template<int DIR>
__device__ __forceinline__ void warp_fft128(float2 v[4], const float2* __restrict__ tw, int t) {
    float2 t0 = cadd(v[0], v[2]);
    float2 t1 = csub(v[0], v[2]);
    float2 t2 = cadd(v[1], v[3]);
    float2 t3 = csub(v[1], v[3]);
    float2 t3r = DIR ? make_float2(-t3.y, t3.x) : make_float2(t3.y, -t3.x);
    v[0] = cadd(t0, t2);
    v[2] = csub(t0, t2);
    v[1] = cadd(t1, t3r);
    v[3] = csub(t1, t3r);
    float2 w1 = tw[t], w2 = tw[2*t];
    v[1] = cmul(v[1], w1);
    v[2] = cmul(v[2], w2);
    v[3] = cmul(v[3], cmul(w1, w2));
#pragma unroll
    for (int d = 16; d >= 1; d >>= 1) {
        int m = (t & (d-1)) * (16/d);
        float2 w = tw[4*m];
        bool hi = (t & d) != 0;
        float s = hi ? -1.f : 1.f;
#pragma unroll
        for (int r = 0; r < 4; r++) {
            float2 p;
            p.x = __shfl_xor_sync(0xffffffffu, v[r].x, d);
            p.y = __shfl_xor_sync(0xffffffffu, v[r].y, d);
            float2 tmp = make_float2(p.x + s*v[r].x, p.y + s*v[r].y);
            v[r] = hi ? cmul(tmp, w) : tmp;
        }
    }
}

// Mirror-DIT inverse: consumes digit-reversed layout, produces natural order.
__device__ __forceinline__ void warp_ifft128_rev(float2 v[4], const float2* __restrict__ twp, int t) {
#pragma unroll
    for (int d = 1; d <= 16; d <<= 1) {
        int m = (t & (d-1)) * (16/d);
        float2 w = twp[4*m];
        bool hi = (t & d) != 0;
#pragma unroll
        for (int r = 0; r < 4; r++) {
            float2 u = hi ? cmul(v[r], w) : v[r];
            float2 p;
            p.x = __shfl_xor_sync(0xffffffffu, u.x, d);
            p.y = __shfl_xor_sync(0xffffffffu, u.y, d);
            v[r] = hi ? csub(p, u) : cadd(u, p);
        }
    }
    float2 w1 = twp[t], w2 = twp[2*t];
    v[1] = cmul(v[1], w1);
    v[2] = cmul(v[2], w2);
    v[3] = cmul(v[3], cmul(w1, w2));
    float2 t0 = cadd(v[0], v[2]), t1 = csub(v[0], v[2]);
    float2 t2 = cadd(v[1], v[3]), t3 = csub(v[1], v[3]);
    float2 t3r = make_float2(-t3.y, t3.x);
    v[0] = cadd(t0, t2);
    v[1] = cadd(t1, t3r);
    v[2] = csub(t0, t2);
    v[3] = csub(t1, t3r);
}

// ---------------------------------------------------------------- zero scratch
__global__ void k_zero() {
    int i = blockIdx.x * blockDim.x + threadIdx.x;
    float4* p = (float4*)d_ras;
    int n4 = 6*VOL/4;
    for (int k = i; k < n4; k += gridDim.x * blockDim.x)
        p[k] = make_float4(0.f, 0.f, 0.f, 0.f);
    if (i < 2) d_accum[i] = 0.f;
}

// ---------------------------------------------------------------- scatter
__global__ void k_scatter(const float* __restrict__ V, const float* __restrict__ N) {
    int id = blockIdx.x * blockDim.x + threadIdx.x;
    if (id >= 2*NPTS) return;
    int b = id >> 16;
    float px = V[3*id+0]*128.f, py = V[3*id+1]*128.f, pz = V[3*id+2]*128.f;
    int ix0 = max(0, min(127, (int)floorf(px)));
    int iy0 = max(0, min(127, (int)floorf(py)));
    int iz0 = max(0, min(127, (int)floorf(pz)));
    float fx = px - (float)ix0, fy = py - (float)iy0, fz = pz - (float)iz0;
    int ix[2] = {ix0, (ix0+1)&127};
    int iy[2] = {iy0, (iy0+1)&127};
    int iz[2] = {pz4(iz0), pz4((iz0+1)&127)};       // d_ras permuted z
    float wx[2] = {1.f-fx, fx}, wy[2] = {1.f-fy, fy}, wz[2] = {1.f-fz, fz};
    float nx = N[3*id+0], ny = N[3*id+1], nz = N[3*id+2];
    float* r = d_ras + (size_t)b*3*VOL;
#pragma unroll
    for (int cx = 0; cx < 2; cx++)
#pragma unroll
        for (int cy = 0; cy < 2; cy++)
#pragma unroll
            for (int cz = 0; cz < 2; cz++) {
                int sp = (ix[cx]*NRES + iy[cy])*NRES + iz[cz];
                float w = wx[cx]*wy[cy]*wz[cz];
                atomicAdd(r + sp,          w*nx);
                atomicAdd(r + VOL + sp,    w*ny);
                atomicAdd(r + 2*VOL + sp,  w*nz);
            }
}

// --------------- K1: packed-pair real z-FFTs + Hermitian split + y-FFT
__global__ void __launch_bounds__(512, 3) k_fwdZY() {
    extern __shared__ float2 sh[];              // 64 * K1PD float2
    __shared__ float2 tw[64];
    int tid = threadIdx.x, w = tid >> 5, t = tid & 31;
    build_tw64(tw, tid, -1.f);
    __syncthreads();
    int x = blockIdx.x, bc = blockIdx.y;
    const float* base = d_ras + (size_t)(bc*NRES + x) * NRES * NRES;
    // stage 1: 64 packed pairs (y=2m, 2m+1); pz4 layout -> float4 loads give
    // v[r] = x[t+32r] (FFT input convention) directly.
    for (int j = 0; j < 4; j++) {
        int m = w + 16*j;
        const float4* inA4 = (const float4*)(base + (2*m)*NRES);
        const float4* inB4 = (const float4*)(base + (2*m+1)*NRES);
        float4 A = inA4[t];
        float4 B = inB4[t];
        float2 v[4];
        v[0] = make_float2(A.x, B.x);
        v[1] = make_float2(A.y, B.y);
        v[2] = make_float2(A.z, B.z);
        v[3] = make_float2(A.w, B.w);
        warp_fft128<0>(v, tw, t);
#pragma unroll
        for (int r = 0; r < 4; r++) sh[m*K1PD + t + 32*r] = v[r];   // permuted kz, cf
    }
    __syncthreads();
    // stage 2: y-lines for kz < KZCUT only; stores predicated on ky cutoff
    float2* dstp = d_sp + (size_t)(bc*NRES + x) * NKZ * NRES;
    int half = t >> 1;
    bool odd = (t & 1) != 0;
    int u = bitrev5(t);
    for (int kz = w; kz < KZCUT; kz += 16) {
        int a1 = paddr(kz);
        int a2 = paddr((128 - kz) & 127);
        float fz2 = (float)(kz*kz);
        float2 v[4];
#pragma unroll
        for (int r = 0; r < 4; r++) {
            int m = half + 16*r;                 // y = t+32r, m = y>>1, parity = t&1
            float2 P1 = sh[m*K1PD + a1];
            float2 P2 = sh[m*K1PD + a2];
            if (!odd) v[r] = make_float2(0.5f*(P1.x + P2.x), 0.5f*(P1.y - P2.y));
            else      v[r] = make_float2(0.5f*(P1.y + P2.y), 0.5f*(P2.x - P1.x));
        }
        warp_fft128<0>(v, tw, t);
        float2* dst = dstp + kz*NRES;
#pragma unroll
        for (int r = 0; r < 4; r++) {
            float fy = freq_of(4*u + r);         // freq at address t+32r
            if (fy*fy + fz2 <= CUT2) dst[t + 32*r] = v[r];
        }
    }
}

// ------------- K2: per-line cutoff; sequential fwd X/YZ FFTs + combine + inverse
// Grid y covers only kz < KZCUT. Cut lines: no load, no FFT, no store.
__global__ void __launch_bounds__(256, 5) k_specX() {
    extern __shared__ float2 tile[];            // 2 * K2TS float2 (18 KB)
    __shared__ float2 twf[64];
    __shared__ float2 twi[64];
    int tid = threadIdx.x, l = tid >> 5, t = tid & 31;
    build_tw64(twf, tid, -1.f);
    if (tid >= 64 && tid < 128) build_tw64(twi, tid - 64, 1.f);
    int c = blockIdx.x, kz = blockIdx.y, b = blockIdx.z;
    int kya0 = K2L*c;
    const float TWOPI = 6.28318530717958647f;
    float fz = (float)kz;
    float fz2 = fz*fz;
    float2* tileX  = tile;
    float2* tileYZ = tile + K2TS;
    // ---- load phase: only non-cut lines (ch0 raw; ch1,ch2 combined)
    {
        const float2* src0 = d_sp + ((size_t)(b*3 + 0)*NRES*NKZ + kz)*NRES + kya0;
        const float2* src1 = src0 + (size_t)NRES*NKZ*NRES;
        const float2* src2 = src1 + (size_t)NRES*NKZ*NRES;
        for (int i = tid; i < 128*K2L; i += 256) {
            int xx = i >> 3, kyl = i & 7;
            int kya = kya0 + kyl;
            float fy = freq_of(4*bitrev5(kya & 31) + (kya >> 5));
            if (fy*fy + fz2 > CUT2) continue;          // cut line: no load
            size_t off = (size_t)xx*NKZ*NRES + kyl;
            float2 e1 = src1[off];
            float2 e2 = src2[off];
            tileX[xx*K2P + kyl] = src0[off];
            tileYZ[xx*K2P + kyl] = make_float2(TWOPI*(fy*e1.x + fz*e2.x),
                                               TWOPI*(fy*e1.y + fz*e2.y));
        }
    }
    __syncthreads();
    int kya = kya0 + l;
    int fyi = 4*bitrev5(kya & 31) + (kya >> 5);
    float fy = freq_of(fyi);
    int u = bitrev5(t);
    if (fy*fy + fz2 <= CUT2) {
        // fwd FFT of X channel; park spectrum in own column
        {
            float2 vX[4];
#pragma unroll
            for (int r = 0; r < 4; r++) vX[r] = tileX[(t + 32*r)*K2P + l];
            warp_fft128<0>(vX, twf, t);
#pragma unroll
            for (int r = 0; r < 4; r++) tileX[(t + 32*r)*K2P + l] = vX[r];
        }
        // fwd FFT of YZ channel, then combine with parked X spectrum
        float2 v[4];
#pragma unroll
        for (int r = 0; r < 4; r++) v[r] = tileYZ[(t + 32*r)*K2P + l];
        warp_fft128<0>(v, twf, t);
#pragma unroll
        for (int r = 0; r < 4; r++) {
            float2 xs = tileX[(t + 32*r)*K2P + l];
            int kx = 4*u + r;
            float fx = (float)(kx < 64 ? kx : kx - 128);
            float wx = TWOPI * fx;
            float2 acc = make_float2(wx*xs.x + v[r].x, wx*xs.y + v[r].y);
            float d2 = fx*fx + fy*fy + fz2;
            float G = expf(-0.01220703125f * d2);            // 0.5*(sig*2/128)^2
            float L = -39.478417604357434f * d2 + 1e-6f;     // -4*pi^2*|f|^2 + eps
            v[r] = make_float2(G*acc.y/L, -G*acc.x/L);       // -i*G*acc/L
            if (kx == 0 && fyi == 0 && kz == 0) v[r] = make_float2(0.f, 0.f);
        }
        warp_ifft128_rev(v, twi, t);            // -> natural x order
#pragma unroll
        for (int r = 0; r < 4; r++) tileX[(t + 32*r)*K2P + l] = v[r];
    }
    __syncthreads();
    // store only kept columns (K3 zero-fills the cut ones)
    float2* dst = d_inv1 + (size_t)(b*NKZ + kz)*NRES*NRES + kya0;
    for (int i = tid; i < 128*K2L; i += 256) {
        int xx = i >> 3, kyl = i & 7;
        int kya2 = kya0 + kyl;
        float fyw = freq_of(4*bitrev5(kya2 & 31) + (kya2 >> 5));
        if (fyw*fyw + fz2 > CUT2) continue;
        dst[(size_t)xx*NRES + kyl] = tileX[xx*K2P + kyl];
    }
}

// --------------- K3: inverse y-FFT (mirror-DIT) + packed-pair C2R z-FFTs
__global__ void __launch_bounds__(512, 3) k_invYZ() {
    extern __shared__ float2 sh[];              // 128*65 float2 : sh[y][kz]
    __shared__ float2 twi[64];
    int tid = threadIdx.x, w = tid >> 5, t = tid & 31;
    build_tw64(twi, tid, 1.f);
    __syncthreads();
    int x = blockIdx.x, b = blockIdx.y;
    int u = bitrev5(t);
    // stage 1: ky-lines; cut elements (per-address cutoff) read as zero
    for (int kz = w; kz < NKZ; kz += 16) {
        if (kz < KZCUT) {
            float fz2 = (float)(kz*kz);
            const float2* in = d_inv1 + ((size_t)(b*NKZ + kz)*NRES + x)*NRES;
            float2 v[4];
#pragma unroll
            for (int r = 0; r < 4; r++) {
                float fy = freq_of(4*u + r);     // freq at address t+32r
                v[r] = (fy*fy + fz2 <= CUT2) ? in[t + 32*r] : make_float2(0.f, 0.f);
            }
            warp_ifft128_rev(v, twi, t);        // natural y = t+32r
#pragma unroll
            for (int r = 0; r < 4; r++) sh[(t + 32*r)*NKZ + kz] = v[r];
        } else {
            float2 z0 = make_float2(0.f, 0.f);
#pragma unroll
            for (int r = 0; r < 4; r++) sh[(t + 32*r)*NKZ + kz] = z0;
        }
    }
    __syncthreads();
    // stage 2: 64 packed C2R pairs: G = S_{2m} + i*S_{2m+1}, one inverse FFT.
    // Float4 store at lane t writes z = 4*bitrev5(t)+r -> the pphi layout.
    const float sc = 1.0f / 2097152.0f;         // 1/128^3
    float* outb = d_phi + (size_t)(b*NRES + x) * NRES * NRES;
    for (int j = 0; j < 4; j++) {
        int m = w + 16*j;
        const float2* rowA = sh + (2*m)*NKZ;
        const float2* rowB = rowA + NKZ;
        float2 v[4];
#pragma unroll
        for (int r = 0; r < 4; r++) {
            int k = t + 32*r;
            if (k <= 64) {
                float2 A = rowA[k], B = rowB[k];
                v[r] = make_float2(A.x - B.y, A.y + B.x);
            } else {
                int k2 = 128 - k;
                float2 A = rowA[k2], B = rowB[k2];
                v[r] = make_float2(A.x + B.y, B.x - A.y);
            }
        }
        warp_fft128<1>(v, twi, t);              // v[r] = phi(4*bitrev5(t)+r)
        float4* oA4 = (float4*)(outb + (2*m)*NRES);
        float4* oB4 = (float4*)(outb + (2*m+1)*NRES);
        oA4[t] = make_float4(v[0].x*sc, v[1].x*sc, v[2].x*sc, v[3].x*sc);
        oB4[t] = make_float4(v[0].y*sc, v[1].y*sc, v[2].y*sc, v[3].y*sc);
    }
}

// ---------------------------------------------------------------- gather + mean
__global__ void k_gather(const float* __restrict__ V) {
    __shared__ float red[256];
    int id = blockIdx.x * 256 + threadIdx.x;    // 131072; b uniform per block
    int b = id >> 16;
    float px = V[3*id+0]*128.f, py = V[3*id+1]*128.f, pz = V[3*id+2]*128.f;
    int ix0 = max(0, min(127, (int)floorf(px)));
    int iy0 = max(0, min(127, (int)floorf(py)));
    int iz0 = max(0, min(127, (int)floorf(pz)));
    float fx = px - (float)ix0, fy = py - (float)iy0, fz = pz - (float)iz0;
    int ix[2] = {ix0, (ix0+1)&127};
    int iy[2] = {iy0, (iy0+1)&127};
    int az[2] = {pphi(iz0), pphi((iz0+1)&127)}; // d_phi permuted z addresses
    float wx[2] = {1.f-fx, fx}, wy[2] = {1.f-fy, fy}, wz[2] = {1.f-fz, fz};
    const float* ph = d_phi + (size_t)b*VOL;
    float fv = 0.f;
#pragma unroll
    for (int cx = 0; cx < 2; cx++)
#pragma unroll
        for (int cy = 0; cy < 2; cy++)
#pragma unroll
            for (int cz = 0; cz < 2; cz++)
                fv += wx[cx]*wy[cy]*wz[cz] * ph[(ix[cx]*NRES + iy[cy])*NRES + az[cz]];
    red[threadIdx.x] = fv;
    __syncthreads();
    for (int s = 128; s > 0; s >>= 1) {
        if (threadIdx.x < s) red[threadIdx.x] += red[threadIdx.x + s];
        __syncthreads();
    }
    if (threadIdx.x == 0) atomicAdd(&d_accum[b], red[0]);
}

// ---------------------------------------------------------------- finalize
// One warp per (b,x,y) row. Lane t's float4 holds z = 4*bitrev5(t)+{0..3}
// (contiguous!) -> float4 store to out at row offset bitrev5(t). Both sides
// fully coalesced 128-bit.
__global__ void k_final(float* __restrict__ out) {
    int gw = blockIdx.x * 8 + (threadIdx.x >> 5);    // 32768 rows
    int t = threadIdx.x & 31;
    int b = gw >> 14;
    float off  = d_accum[b] * (1.0f/65536.0f);
    float p000 = d_phi[(size_t)b * VOL];             // pphi(0)=0
    float s = 0.5f / fabsf(p000 - off);
    const float4* in4 = (const float4*)(d_phi + (size_t)gw * NRES);
    float4 v = in4[t];                               // z = 4*bitrev5(t)+r
    float4 o;
    o.x = -(v.x - off) * s;
    o.y = -(v.y - off) * s;
    o.z = -(v.z - off) * s;
    o.w = -(v.w - off) * s;
    float4* out4 = (float4*)(out + (size_t)gw * NRES);
    out4[bitrev5(t)] = o;
}

// ---------------------------------------------------------------- launch
extern "C" void kernel_launch(void* const* d_in, const int* in_sizes, int n_in,
                              void* d_out, int out_size) {
    const float* V = (const float*)d_in[0];
    const float* N = (const float*)d_in[1];
    float* out = (float*)d_out;

    const int k1Bytes = 64*K1PD*sizeof(float2);       // 66048
    const int k3Bytes = NRES*NKZ*sizeof(float2);      // 66560
    const int k2Bytes = 2*K2TS*sizeof(float2);        // 18432
    cudaFuncSetAttribute(k_fwdZY, cudaFuncAttributeMaxDynamicSharedMemorySize, k1Bytes);
    cudaFuncSetAttribute(k_invYZ, cudaFuncAttributeMaxDynamicSharedMemorySize, k3Bytes);

    k_zero<<<4096, 256>>>();
    k_scatter<<<512, 256>>>(V, N);
    k_fwdZY<<<dim3(128, 6), 512, k1Bytes>>>();        // 768 planes
    k_specX<<<dim3(16, KZCUT, 2), 256, k2Bytes>>>();  // only kz < 32
    k_invYZ<<<dim3(128, 2), 512, k3Bytes>>>();        // 256 planes
    k_gather<<<512, 256>>>(V);
    k_final<<<4096, 256>>>(out);
}

// round 14
// speedup vs baseline: 1.1560x; 1.0358x over previous
#include <cuda_runtime.h>
#include <math.h>

// DPSR: scatter -> 3D rFFT -> spectral Poisson solve -> 3D irFFT -> gather/normalize
// Fused pipeline (3 FFT kernels) + spectral cutoff propagated end-to-end.
//   G = exp(-0.0122*d2) < 5e-6 for fy^2+fz^2 > 1000 -> cut those (ky,kz) lines.
//
// Layouts:
//   d_ras4 [b][x][y][zp] float4 = (Nx,Ny,Nz,pad), zp = pz4(z) = 4*(z&31)+(z>>5).
//     Scatter uses ONE float4 atomic per corner (8/point). K1 lane t loads
//     float4 idx 4t+r -> z = t+32r (FFT input convention), all 3 channels.
//   d_sp/d_inv1 ky axis DIGIT-REVERSED: address a holds f = 4*bitrev5(a&31)+(a>>5).
//   d_phi z axis pphi-permuted: address 4t+r holds z = 4*bitrev5(t)+r.
//   K1 smem spectrum COMPACT: slot(f) = f (f<32) / f-64 (f>=96); 64 slots.
//   K3 smem holds only kz<32 columns (rest identically zero).

#define NRES 128
#define NKZ  65
#define VOL  (NRES*NRES*NRES)
#define NPTS 65536
#define K2L  8           // kya lines per K2 block
#define K2P  9           // K2 tile pad stride
#define K2TS (128*K2P)   // padded tile size (float2) per channel
#define K1SL 65          // K1 compact smem row stride (64 slots + pad)
#define K1CH (64*K1SL)   // K1 smem floats2 per channel
#define K3ST 33          // K3 smem row stride (32 kz + pad)
#define CUT2 1000.0f     // skip line if fy^2+fz^2 > CUT2  (G < 5e-6)
#define KZCUT 32         // kz >= KZCUT -> fz^2 > CUT2 for all ky

__device__ float4 d_ras4[2*VOL];                // [b][x][y][zp] (64 MB)
__device__ float2 d_sp[6*NRES*NKZ*NRES];        // [bc][x][kz][kya]
__device__ float2 d_inv1[2*NKZ*NRES*NRES];      // [b][kz][x][kya]
__device__ __align__(16) float  d_phi[2*VOL];   // [b][x][y][z-pphi]
__device__ float  d_accum[2];

__device__ __forceinline__ float2 cmul(float2 a, float2 b) {
    return make_float2(a.x*b.x - a.y*b.y, a.x*b.y + a.y*b.x);
}
__device__ __forceinline__ float2 cadd(float2 a, float2 b) { return make_float2(a.x+b.x, a.y+b.y); }
__device__ __forceinline__ float2 csub(float2 a, float2 b) { return make_float2(a.x-b.x, a.y-b.y); }
__device__ __forceinline__ int bitrev5(int t) { return (int)(__brev((unsigned)t) >> 27); }
__device__ __forceinline__ int pz4(int z) { return ((z & 31) << 2) | (z >> 5); }
__device__ __forceinline__ int pphi(int z) { return (bitrev5(z >> 2) << 2) | (z & 3); }
__device__ __forceinline__ float freq_of(int fyi) {
    return (fyi < 64) ? (float)fyi : (float)(fyi - 128);
}

__device__ __forceinline__ void build_tw64(float2* tw, int tid, float sign) {
    if (tid < 64) {
        float s, c;
        sincosf(sign * 6.28318530717958647f * (float)tid * (1.0f/128.0f), &s, &c);
        tw[tid] = make_float2(c, s);
    }
}

// Natural-input warp FFT. Lane t holds v[r]=x[t+32r]; out v[r]=X[4*bitrev5(t)+r].
template<int DIR>
__device__ __forceinline__ void warp_fft128(float2 v[4], const float2* __restrict__ tw, int t) {
    float2 t0 = cadd(v[0], v[2]);
    float2 t1 = csub(v[0], v[2]);
    float2 t2 = cadd(v[1], v[3]);
    float2 t3 = csub(v[1], v[3]);
    float2 t3r = DIR ? make_float2(-t3.y, t3.x) : make_float2(t3.y, -t3.x);
    v[0] = cadd(t0, t2);
    v[2] = csub(t0, t2);
    v[1] = cadd(t1, t3r);
    v[3] = csub(t1, t3r);
    float2 w1 = tw[t], w2 = tw[2*t];
    v[1] = cmul(v[1], w1);
    v[2] = cmul(v[2], w2);
    v[3] = cmul(v[3], cmul(w1, w2));
#pragma unroll
    for (int d = 16; d >= 1; d >>= 1) {
        int m = (t & (d-1)) * (16/d);
        float2 w = tw[4*m];
        bool hi = (t & d) != 0;
        float s = hi ? -1.f : 1.f;
#pragma unroll
        for (int r = 0; r < 4; r++) {
            float2 p;
            p.x = __shfl_xor_sync(0xffffffffu, v[r].x, d);
            p.y = __shfl_xor_sync(0xffffffffu, v[r].y, d);
            float2 tmp = make_float2(p.x + s*v[r].x, p.y + s*v[r].y);
            v[r] = hi ? cmul(tmp, w) : tmp;
        }
    }
}

// Mirror-DIT inverse: consumes digit-reversed layout, produces natural order.
__device__ __forceinline__ void warp_ifft128_rev(float2 v[4], const float2* __restrict__ twp, int t) {
#pragma unroll
    for (int d = 1; d <= 16; d <<= 1) {
        int m = (t & (d-1)) * (16/d);
        float2 w = twp[4*m];
        bool hi = (t & d) != 0;
#pragma unroll
        for (int r = 0; r < 4; r++) {
            float2 u = hi ? cmul(v[r], w) : v[r];
            float2 p;
            p.x = __shfl_xor_sync(0xffffffffu, u.x, d);
            p.y = __shfl_xor_sync(0xffffffffu, u.y, d);
            v[r] = hi ? csub(p, u) : cadd(u, p);
        }
    }
    float2 w1 = twp[t], w2 = twp[2*t];
    v[1] = cmul(v[1], w1);
    v[2] = cmul(v[2], w2);
    v[3] = cmul(v[3], cmul(w1, w2));
    float2 t0 = cadd(v[0], v[2]), t1 = csub(v[0], v[2]);
    float2 t2 = cadd(v[1], v[3]), t3 = csub(v[1], v[3]);
    float2 t3r = make_float2(-t3.y, t3.x);
    v[0] = cadd(t0, t2);
    v[1] = cadd(t1, t3r);
    v[2] = csub(t0, t2);
    v[3] = csub(t1, t3r);
}

// ---------------------------------------------------------------- zero scratch
__global__ void k_zero() {
    int i = blockIdx.x * blockDim.x + threadIdx.x;
    int n = 2*VOL;
    for (int k = i; k < n; k += gridDim.x * blockDim.x)
        d_ras4[k] = make_float4(0.f, 0.f, 0.f, 0.f);
    if (i < 2) d_accum[i] = 0.f;
}

// ------------------------------------------- scatter: 8 float4 atomics / point
__global__ void k_scatter(const float* __restrict__ V, const float* __restrict__ N) {
    int id = blockIdx.x * blockDim.x + threadIdx.x;
    if (id >= 2*NPTS) return;
    int b = id >> 16;
    float px = V[3*id+0]*128.f, py = V[3*id+1]*128.f, pz = V[3*id+2]*128.f;
    int ix0 = max(0, min(127, (int)floorf(px)));
    int iy0 = max(0, min(127, (int)floorf(py)));
    int iz0 = max(0, min(127, (int)floorf(pz)));
    float fx = px - (float)ix0, fy = py - (float)iy0, fz = pz - (float)iz0;
    int ix[2] = {ix0, (ix0+1)&127};
    int iy[2] = {iy0, (iy0+1)&127};
    int iz[2] = {pz4(iz0), pz4((iz0+1)&127)};
    float wx[2] = {1.f-fx, fx}, wy[2] = {1.f-fy, fy}, wz[2] = {1.f-fz, fz};
    float nx = N[3*id+0], ny = N[3*id+1], nz = N[3*id+2];
    float4* r4 = d_ras4 + (size_t)b*VOL;
#pragma unroll
    for (int cx = 0; cx < 2; cx++)
#pragma unroll
        for (int cy = 0; cy < 2; cy++)
#pragma unroll
            for (int cz = 0; cz < 2; cz++) {
                int sp = (ix[cx]*NRES + iy[cy])*NRES + iz[cz];
                float w = wx[cx]*wy[cy]*wz[cz];
                atomicAdd(r4 + sp, make_float4(w*nx, w*ny, w*nz, 0.f));
            }
}

// --------------- K1: 3-channel packed-pair z-FFTs + Hermitian split + y-FFT
// One block per (b,x). Loads each float4 once; compact 64-slot spectra in smem.
__global__ void __launch_bounds__(512, 2) k_fwdZY() {
    extern __shared__ float2 sh[];              // 3 * K1CH float2 (~100 KB)
    __shared__ float2 tw[64];
    int tid = threadIdx.x, w = tid >> 5, t = tid & 31;
    build_tw64(tw, tid, -1.f);
    __syncthreads();
    int x = blockIdx.x, b = blockIdx.y;
    const float4* base4 = d_ras4 + (size_t)(b*NRES + x) * NRES * NRES;
    int u = bitrev5(t);
    int tm = t & 3;
    bool kept = (tm == 0) || (tm == 3);         // outputs f<32 or f>=96
    int slotbase = 4 * (u & 15);                // slot = f (f<32) / f-64 (f>=96)
    // stage 1: 64 y-pairs; each float4 load gives all 3 channels of one z
    for (int j = 0; j < 4; j++) {
        int m = w + 16*j;
        const float4* A4 = base4 + (2*m)*NRES;
        const float4* B4 = base4 + (2*m+1)*NRES;
        float4 A[4], B[4];
#pragma unroll
        for (int r = 0; r < 4; r++) { A[r] = A4[4*t + r]; B[r] = B4[4*t + r]; }
#pragma unroll
        for (int ch = 0; ch < 3; ch++) {
            float2 v[4];
#pragma unroll
            for (int r = 0; r < 4; r++) {
                float a = (ch == 0) ? A[r].x : (ch == 1) ? A[r].y : A[r].z;
                float bb = (ch == 0) ? B[r].x : (ch == 1) ? B[r].y : B[r].z;
                v[r] = make_float2(a, bb);
            }
            warp_fft128<0>(v, tw, t);
            if (kept) {
                float2* shc = sh + ch*K1CH + m*K1SL;
#pragma unroll
                for (int r = 0; r < 4; r++) shc[slotbase + r] = v[r];
            }
        }
    }
    __syncthreads();
    // stage 2: 3 ch x 32 kz y-lines; Hermitian split from compact slots
    int half = t >> 1;
    bool odd = (t & 1) != 0;
    for (int line = w; line < 96; line += 16) {
        int ch = line >> 5, kz = line & 31;
        const float2* shc = sh + ch*K1CH;
        int a1 = kz;
        int a2 = (kz == 0) ? 0 : (64 - kz);
        float fz2 = (float)(kz*kz);
        float2 v[4];
#pragma unroll
        for (int r = 0; r < 4; r++) {
            int m = half + 16*r;                 // y = t+32r, parity = t&1
            float2 P1 = shc[m*K1SL + a1];
            float2 P2 = shc[m*K1SL + a2];
            if (!odd) v[r] = make_float2(0.5f*(P1.x + P2.x), 0.5f*(P1.y - P2.y));
            else      v[r] = make_float2(0.5f*(P1.y + P2.y), 0.5f*(P2.x - P1.x));
        }
        warp_fft128<0>(v, tw, t);
        float2* dst = d_sp + (((size_t)(b*3 + ch)*NRES + x)*NKZ + kz)*NRES;
#pragma unroll
        for (int r = 0; r < 4; r++) {
            float fy = freq_of(4*u + r);         // freq at address t+32r
            if (fy*fy + fz2 <= CUT2) dst[t + 32*r] = v[r];
        }
    }
}

// ------------- K2: per-line cutoff; sequential fwd X/YZ FFTs + combine + inverse
__global__ void __launch_bounds__(256, 5) k_specX() {
    extern __shared__ float2 tile[];            // 2 * K2TS float2 (18 KB)
    __shared__ float2 twf[64];
    __shared__ float2 twi[64];
    int tid = threadIdx.x, l = tid >> 5, t = tid & 31;
    build_tw64(twf, tid, -1.f);
    if (tid >= 64 && tid < 128) build_tw64(twi, tid - 64, 1.f);
    int c = blockIdx.x, kz = blockIdx.y, b = blockIdx.z;
    int kya0 = K2L*c;
    const float TWOPI = 6.28318530717958647f;
    float fz = (float)kz;
    float fz2 = fz*fz;
    float2* tileX  = tile;
    float2* tileYZ = tile + K2TS;
    {
        const float2* src0 = d_sp + ((size_t)(b*3 + 0)*NRES*NKZ + kz)*NRES + kya0;
        const float2* src1 = src0 + (size_t)NRES*NKZ*NRES;
        const float2* src2 = src1 + (size_t)NRES*NKZ*NRES;
        for (int i = tid; i < 128*K2L; i += 256) {
            int xx = i >> 3, kyl = i & 7;
            int kya = kya0 + kyl;
            float fy = freq_of(4*bitrev5(kya & 31) + (kya >> 5));
            if (fy*fy + fz2 > CUT2) continue;          // cut line: no load
            size_t off = (size_t)xx*NKZ*NRES + kyl;
            float2 e1 = src1[off];
            float2 e2 = src2[off];
            tileX[xx*K2P + kyl] = src0[off];
            tileYZ[xx*K2P + kyl] = make_float2(TWOPI*(fy*e1.x + fz*e2.x),
                                               TWOPI*(fy*e1.y + fz*e2.y));
        }
    }
    __syncthreads();
    int kya = kya0 + l;
    int fyi = 4*bitrev5(kya & 31) + (kya >> 5);
    float fy = freq_of(fyi);
    int u = bitrev5(t);
    if (fy*fy + fz2 <= CUT2) {
        {
            float2 vX[4];
#pragma unroll
            for (int r = 0; r < 4; r++) vX[r] = tileX[(t + 32*r)*K2P + l];
            warp_fft128<0>(vX, twf, t);
#pragma unroll
            for (int r = 0; r < 4; r++) tileX[(t + 32*r)*K2P + l] = vX[r];
        }
        float2 v[4];
#pragma unroll
        for (int r = 0; r < 4; r++) v[r] = tileYZ[(t + 32*r)*K2P + l];
        warp_fft128<0>(v, twf, t);
#pragma unroll
        for (int r = 0; r < 4; r++) {
            float2 xs = tileX[(t + 32*r)*K2P + l];
            int kx = 4*u + r;
            float fx = (float)(kx < 64 ? kx : kx - 128);
            float wx = TWOPI * fx;
            float2 acc = make_float2(wx*xs.x + v[r].x, wx*xs.y + v[r].y);
            float d2 = fx*fx + fy*fy + fz2;
            float G = expf(-0.01220703125f * d2);            // 0.5*(sig*2/128)^2
            float L = -39.478417604357434f * d2 + 1e-6f;     // -4*pi^2*|f|^2 + eps
            v[r] = make_float2(G*acc.y/L, -G*acc.x/L);       // -i*G*acc/L
            if (kx == 0 && fyi == 0 && kz == 0) v[r] = make_float2(0.f, 0.f);
        }
        warp_ifft128_rev(v, twi, t);            // -> natural x order
#pragma unroll
        for (int r = 0; r < 4; r++) tileX[(t + 32*r)*K2P + l] = v[r];
    }
    __syncthreads();
    float2* dst = d_inv1 + (size_t)(b*NKZ + kz)*NRES*NRES + kya0;
    for (int i = tid; i < 128*K2L; i += 256) {
        int xx = i >> 3, kyl = i & 7;
        int kya2 = kya0 + kyl;
        float fyw = freq_of(4*bitrev5(kya2 & 31) + (kya2 >> 5));
        if (fyw*fyw + fz2 > CUT2) continue;
        dst[(size_t)xx*NRES + kyl] = tileX[xx*K2P + kyl];
    }
}

// --------------- K3: inverse y-FFT (mirror-DIT) + packed-pair C2R z-FFTs
// Compact smem: only kz<32 columns (rest identically zero).
__global__ void __launch_bounds__(512, 3) k_invYZ() {
    extern __shared__ float2 sh[];              // 128 * K3ST float2 (~34 KB)
    __shared__ float2 twi[64];
    int tid = threadIdx.x, w = tid >> 5, t = tid & 31;
    build_tw64(twi, tid, 1.f);
    __syncthreads();
    int x = blockIdx.x, b = blockIdx.y;
    int u = bitrev5(t);
    // stage 1: ky-lines for kz<32 only (2 iterations per warp)
    for (int kz = w; kz < KZCUT; kz += 16) {
        float fz2 = (float)(kz*kz);
        const float2* in = d_inv1 + ((size_t)(b*NKZ + kz)*NRES + x)*NRES;
        float2 v[4];
#pragma unroll
        for (int r = 0; r < 4; r++) {
            float fy = freq_of(4*u + r);         // freq at address t+32r
            v[r] = (fy*fy + fz2 <= CUT2) ? in[t + 32*r] : make_float2(0.f, 0.f);
        }
        warp_ifft128_rev(v, twi, t);            // natural y = t+32r
#pragma unroll
        for (int r = 0; r < 4; r++) sh[(t + 32*r)*K3ST + kz] = v[r];
    }
    __syncthreads();
    // stage 2: 64 packed C2R pairs. Spectrum zero for kz in [32,64]:
    //   v[0] = combine(row[t]); v[1] = v[2] = 0; v[3] = conj-combine(row[32-t]).
    const float sc = 1.0f / 2097152.0f;         // 1/128^3
    float* outb = d_phi + (size_t)(b*NRES + x) * NRES * NRES;
    for (int j = 0; j < 4; j++) {
        int m = w + 16*j;
        const float2* rowA = sh + (2*m)*K3ST;
        const float2* rowB = rowA + K3ST;
        float2 v[4];
        {
            float2 A = rowA[t], B = rowB[t];
            v[0] = make_float2(A.x - B.y, A.y + B.x);
        }
        v[1] = make_float2(0.f, 0.f);
        v[2] = make_float2(0.f, 0.f);
        if (t == 0) v[3] = make_float2(0.f, 0.f);
        else {
            float2 A = rowA[32 - t], B = rowB[32 - t];
            v[3] = make_float2(A.x + B.y, B.x - A.y);
        }
        warp_fft128<1>(v, twi, t);              // v[r] = phi(4*bitrev5(t)+r)
        float4* oA4 = (float4*)(outb + (2*m)*NRES);
        float4* oB4 = (float4*)(outb + (2*m+1)*NRES);
        oA4[t] = make_float4(v[0].x*sc, v[1].x*sc, v[2].x*sc, v[3].x*sc);
        oB4[t] = make_float4(v[0].y*sc, v[1].y*sc, v[2].y*sc, v[3].y*sc);
    }
}

// ---------------------------------------------------------------- gather + mean
__global__ void k_gather(const float* __restrict__ V) {
    __shared__ float red[256];
    int id = blockIdx.x * 256 + threadIdx.x;    // 131072; b uniform per block
    int b = id >> 16;
    float px = V[3*id+0]*128.f, py = V[3*id+1]*128.f, pz = V[3*id+2]*128.f;
    int ix0 = max(0, min(127, (int)floorf(px)));
    int iy0 = max(0, min(127, (int)floorf(py)));
    int iz0 = max(0, min(127, (int)floorf(pz)));
    float fx = px - (float)ix0, fy = py - (float)iy0, fz = pz - (float)iz0;
    int ix[2] = {ix0, (ix0+1)&127};
    int iy[2] = {iy0, (iy0+1)&127};
    int az[2] = {pphi(iz0), pphi((iz0+1)&127)};
    float wx[2] = {1.f-fx, fx}, wy[2] = {1.f-fy, fy}, wz[2] = {1.f-fz, fz};
    const float* ph = d_phi + (size_t)b*VOL;
    float fv = 0.f;
#pragma unroll
    for (int cx = 0; cx < 2; cx++)
#pragma unroll
        for (int cy = 0; cy < 2; cy++)
#pragma unroll
            for (int cz = 0; cz < 2; cz++)
                fv += wx[cx]*wy[cy]*wz[cz] * ph[(ix[cx]*NRES + iy[cy])*NRES + az[cz]];
    red[threadIdx.x] = fv;
    __syncthreads();
    for (int s = 128; s > 0; s >>= 1) {
        if (threadIdx.x < s) red[threadIdx.x] += red[threadIdx.x + s];
        __syncthreads();
    }
    if (threadIdx.x == 0) atomicAdd(&d_accum[b], red[0]);
}

// ---------------------------------------------------------------- finalize
__global__ void k_final(float* __restrict__ out) {
    int gw = blockIdx.x * 8 + (threadIdx.x >> 5);    // 32768 rows
    int t = threadIdx.x & 31;
    int b = gw >> 14;
    float off  = d_accum[b] * (1.0f/65536.0f);
    float p000 = d_phi[(size_t)b * VOL];             // pphi(0)=0
    float s = 0.5f / fabsf(p000 - off);
    const float4* in4 = (const float4*)(d_phi + (size_t)gw * NRES);
    float4 v = in4[t];                               // z = 4*bitrev5(t)+r
    float4 o;
    o.x = -(v.x - off) * s;
    o.y = -(v.y - off) * s;
    o.z = -(v.z - off) * s;
    o.w = -(v.w - off) * s;
    float4* out4 = (float4*)(out + (size_t)gw * NRES);
    out4[bitrev5(t)] = o;
}

// ---------------------------------------------------------------- launch
extern "C" void kernel_launch(void* const* d_in, const int* in_sizes, int n_in,
                              void* d_out, int out_size) {
    const float* V = (const float*)d_in[0];
    const float* N = (const float*)d_in[1];
    float* out = (float*)d_out;

    const int k1Bytes = 3*K1CH*sizeof(float2);        // 99840
    const int k3Bytes = 128*K3ST*sizeof(float2);      // 33792
    const int k2Bytes = 2*K2TS*sizeof(float2);        // 18432
    cudaFuncSetAttribute(k_fwdZY, cudaFuncAttributeMaxDynamicSharedMemorySize, k1Bytes);
    cudaFuncSetAttribute(k_invYZ, cudaFuncAttributeMaxDynamicSharedMemorySize, k3Bytes);

    k_zero<<<4096, 256>>>();
    k_scatter<<<512, 256>>>(V, N);
    k_fwdZY<<<dim3(128, 2), 512, k1Bytes>>>();        // 256 (b,x) slabs, 3 ch each
    k_specX<<<dim3(16, KZCUT, 2), 256, k2Bytes>>>();  // only kz < 32
    k_invYZ<<<dim3(128, 2), 512, k3Bytes>>>();        // 256 planes
    k_gather<<<512, 256>>>(V);
    k_final<<<4096, 256>>>(out);
}

// round 15
// speedup vs baseline: 1.1841x; 1.0242x over previous
#include <cuda_runtime.h>
#include <math.h>

// DPSR: scatter -> 3D rFFT -> spectral Poisson solve -> 3D irFFT -> gather/normalize
// Fused pipeline (3 FFT kernels) + spectral cutoff propagated end-to-end.
//   G = exp(-0.0122*d2) < 5e-6 for fy^2+fz^2 > 1000 -> cut those (ky,kz) lines.
//
// Layouts:
//   Raster planar-split (no pad waste): d_rasXY float2 (Nx,Ny) + d_rasZ float,
//     both [b][x][y][zp] with zp = pz4(z) = 4*(z&31)+(z>>5). Scatter: one
//     float2 atomic + one float atomic per corner. K1 lane t loads 2 float4
//     (XY) + 1 float4 (Z) per row -> z = t+32r for all 3 channels.
//   d_sp/d_inv1 ky axis DIGIT-REVERSED: address a holds f = 4*bitrev5(a&31)+(a>>5).
//   d_phi z axis pphi-permuted: address 4t+r holds z = 4*bitrev5(t)+r.
//   K1 smem spectrum COMPACT: slot(f) = f (f<32) / f-64 (f>=96); 64 slots.
//   K3 smem holds only kz<32 columns (rest identically zero).

#define NRES 128
#define NKZ  65
#define VOL  (NRES*NRES*NRES)
#define NPTS 65536
#define K2L  4           // kya lines per K2 block (128-thread blocks)
#define K2P  5           // K2 tile pad stride
#define K2TS (128*K2P)   // padded tile size (float2) per channel
#define K1SL 65          // K1 compact smem row stride (64 slots + pad)
#define K1CH (64*K1SL)   // K1 smem float2 per channel
#define K3ST 33          // K3 smem row stride (32 kz + pad)
#define CUT2 1000.0f     // skip line if fy^2+fz^2 > CUT2  (G < 5e-6)
#define KZCUT 32         // kz >= KZCUT -> fz^2 > CUT2 for all ky

__device__ __align__(16) float2 d_rasXY[2*VOL]; // [b][x][y][zp] (33.5 MB)
__device__ __align__(16) float  d_rasZ[2*VOL];  // [b][x][y][zp] (16.8 MB)
__device__ float2 d_sp[6*NRES*NKZ*NRES];        // [bc][x][kz][kya]
__device__ float2 d_inv1[2*NKZ*NRES*NRES];      // [b][kz][x][kya]
__device__ __align__(16) float  d_phi[2*VOL];   // [b][x][y][z-pphi]
__device__ float  d_accum[2];

__device__ __forceinline__ float2 cmul(float2 a, float2 b) {
    return make_float2(a.x*b.x - a.y*b.y, a.x*b.y + a.y*b.x);
}
__device__ __forceinline__ float2 cadd(float2 a, float2 b) { return make_float2(a.x+b.x, a.y+b.y); }
__device__ __forceinline__ float2 csub(float2 a, float2 b) { return make_float2(a.x-b.x, a.y-b.y); }
__device__ __forceinline__ int bitrev5(int t) { return (int)(__brev((unsigned)t) >> 27); }
__device__ __forceinline__ int pz4(int z) { return ((z & 31) << 2) | (z >> 5); }
__device__ __forceinline__ int pphi(int z) { return (bitrev5(z >> 2) << 2) | (z & 3); }
__device__ __forceinline__ float freq_of(int fyi) {
    return (fyi < 64) ? (float)fyi : (float)(fyi - 128);
}

__device__ __forceinline__ void build_tw64(float2* tw, int tid, float sign) {
    if (tid < 64) {
        float s, c;
        sincosf(sign * 6.28318530717958647f * (float)tid * (1.0f/128.0f), &s, &c);
        tw[tid] = make_float2(c, s);
    }
}

// Natural-input warp FFT. Lane t holds v[r]=x[t+32r]; out v[r]=X[4*bitrev5(t)+r].
template<int DIR>
__device__ __forceinline__ void warp_fft128(float2 v[4], const float2* __restrict__ tw, int t) {
    float2 t0 = cadd(v[0], v[2]);
    float2 t1 = csub(v[0], v[2]);
    float2 t2 = cadd(v[1], v[3]);
    float2 t3 = csub(v[1], v[3]);
    float2 t3r = DIR ? make_float2(-t3.y, t3.x) : make_float2(t3.y, -t3.x);
    v[0] = cadd(t0, t2);
    v[2] = csub(t0, t2);
    v[1] = cadd(t1, t3r);
    v[3] = csub(t1, t3r);
    float2 w1 = tw[t], w2 = tw[2*t];
    v[1] = cmul(v[1], w1);
    v[2] = cmul(v[2], w2);
    v[3] = cmul(v[3], cmul(w1, w2));
#pragma unroll
    for (int d = 16; d >= 1; d >>= 1) {
        int m = (t & (d-1)) * (16/d);
        float2 w = tw[4*m];
        bool hi = (t & d) != 0;
        float s = hi ? -1.f : 1.f;
#pragma unroll
        for (int r = 0; r < 4; r++) {
            float2 p;
            p.x = __shfl_xor_sync(0xffffffffu, v[r].x, d);
            p.y = __shfl_xor_sync(0xffffffffu, v[r].y, d);
            float2 tmp = make_float2(p.x + s*v[r].x, p.y + s*v[r].y);
            v[r] = hi ? cmul(tmp, w) : tmp;
        }
    }
}

// Mirror-DIT inverse: consumes digit-reversed layout, produces natural order.
__device__ __forceinline__ void warp_ifft128_rev(float2 v[4], const float2* __restrict__ twp, int t) {
#pragma unroll
    for (int d = 1; d <= 16; d <<= 1) {
        int m = (t & (d-1)) * (16/d);
        float2 w = twp[4*m];
        bool hi = (t & d) != 0;
#pragma unroll
        for (int r = 0; r < 4; r++) {
            float2 u = hi ? cmul(v[r], w) : v[r];
            float2 p;
            p.x = __shfl_xor_sync(0xffffffffu, u.x, d);
            p.y = __shfl_xor_sync(0xffffffffu, u.y, d);
            v[r] = hi ? csub(p, u) : cadd(u, p);
        }
    }
    float2 w1 = twp[t], w2 = twp[2*t];
    v[1] = cmul(v[1], w1);
    v[2] = cmul(v[2], w2);
    v[3] = cmul(v[3], cmul(w1, w2));
    float2 t0 = cadd(v[0], v[2]), t1 = csub(v[0], v[2]);
    float2 t2 = cadd(v[1], v[3]), t3 = csub(v[1], v[3]);
    float2 t3r = make_float2(-t3.y, t3.x);
    v[0] = cadd(t0, t2);
    v[1] = cadd(t1, t3r);
    v[2] = csub(t0, t2);
    v[3] = csub(t1, t3r);
}

// ---------------------------------------------------------------- zero scratch
__global__ void k_zero() {
    int i = blockIdx.x * blockDim.x + threadIdx.x;
    int stride = gridDim.x * blockDim.x;
    float4 z4 = make_float4(0.f, 0.f, 0.f, 0.f);
    float4* p = (float4*)d_rasXY;               // VOL float4s
    for (int k = i; k < VOL; k += stride) p[k] = z4;
    float4* q = (float4*)d_rasZ;                // VOL/2 float4s
    for (int k = i; k < VOL/2; k += stride) q[k] = z4;
    if (i < 2) d_accum[i] = 0.f;
}

// --------------------- scatter: float2 + float atomic per corner (3 elem-adds)
__global__ void k_scatter(const float* __restrict__ V, const float* __restrict__ N) {
    int id = blockIdx.x * blockDim.x + threadIdx.x;
    if (id >= 2*NPTS) return;
    int b = id >> 16;
    float px = V[3*id+0]*128.f, py = V[3*id+1]*128.f, pz = V[3*id+2]*128.f;
    int ix0 = max(0, min(127, (int)floorf(px)));
    int iy0 = max(0, min(127, (int)floorf(py)));
    int iz0 = max(0, min(127, (int)floorf(pz)));
    float fx = px - (float)ix0, fy = py - (float)iy0, fz = pz - (float)iz0;
    int ix[2] = {ix0, (ix0+1)&127};
    int iy[2] = {iy0, (iy0+1)&127};
    int iz[2] = {pz4(iz0), pz4((iz0+1)&127)};
    float wx[2] = {1.f-fx, fx}, wy[2] = {1.f-fy, fy}, wz[2] = {1.f-fz, fz};
    float nx = N[3*id+0], ny = N[3*id+1], nz = N[3*id+2];
    float2* rxy = d_rasXY + (size_t)b*VOL;
    float*  rz  = d_rasZ  + (size_t)b*VOL;
#pragma unroll
    for (int cx = 0; cx < 2; cx++)
#pragma unroll
        for (int cy = 0; cy < 2; cy++)
#pragma unroll
            for (int cz = 0; cz < 2; cz++) {
                int sp = (ix[cx]*NRES + iy[cy])*NRES + iz[cz];
                float w = wx[cx]*wy[cy]*wz[cz];
                atomicAdd(rxy + sp, make_float2(w*nx, w*ny));
                atomicAdd(rz + sp, w*nz);
            }
}

// --------------- K1: 3-channel packed-pair z-FFTs + Hermitian split + y-FFT
// One block per (b,x). Compact 64-slot spectra in smem; vectorized loads.
__global__ void __launch_bounds__(512, 2) k_fwdZY() {
    extern __shared__ float2 sh[];              // 3 * K1CH float2 (~100 KB)
    __shared__ float2 tw[64];
    int tid = threadIdx.x, w = tid >> 5, t = tid & 31;
    build_tw64(tw, tid, -1.f);
    __syncthreads();
    int x = blockIdx.x, b = blockIdx.y;
    const float2* baseXY = d_rasXY + (size_t)(b*NRES + x) * NRES * NRES;
    const float*  baseZ  = d_rasZ  + (size_t)(b*NRES + x) * NRES * NRES;
    int u = bitrev5(t);
    int tm = t & 3;
    bool kept = (tm == 0) || (tm == 3);         // outputs f<32 or f>=96
    int slotbase = 4 * (u & 15);                // slot = f (f<32) / f-64 (f>=96)
    // stage 1: 64 y-pairs; lane t covers z = t+32r via contiguous float4 loads
    for (int j = 0; j < 4; j++) {
        int m = w + 16*j;
        const float4* axy = (const float4*)(baseXY + (2*m)*NRES);
        const float4* bxy = (const float4*)(baseXY + (2*m+1)*NRES);
        const float4* az4 = (const float4*)(baseZ + (2*m)*NRES);
        const float4* bz4 = (const float4*)(baseZ + (2*m+1)*NRES);
        float4 a0 = axy[2*t], a1 = axy[2*t + 1];
        float4 b0 = bxy[2*t], b1 = bxy[2*t + 1];
        float4 az = az4[t],   bz = bz4[t];
        // per-channel packed FFTs (A row -> real, B row -> imag)
#pragma unroll
        for (int ch = 0; ch < 3; ch++) {
            float2 v[4];
            if (ch == 0) {
                v[0] = make_float2(a0.x, b0.x);
                v[1] = make_float2(a0.z, b0.z);
                v[2] = make_float2(a1.x, b1.x);
                v[3] = make_float2(a1.z, b1.z);
            } else if (ch == 1) {
                v[0] = make_float2(a0.y, b0.y);
                v[1] = make_float2(a0.w, b0.w);
                v[2] = make_float2(a1.y, b1.y);
                v[3] = make_float2(a1.w, b1.w);
            } else {
                v[0] = make_float2(az.x, bz.x);
                v[1] = make_float2(az.y, bz.y);
                v[2] = make_float2(az.z, bz.z);
                v[3] = make_float2(az.w, bz.w);
            }
            warp_fft128<0>(v, tw, t);
            if (kept) {
                float2* shc = sh + ch*K1CH + m*K1SL;
#pragma unroll
                for (int r = 0; r < 4; r++) shc[slotbase + r] = v[r];
            }
        }
    }
    __syncthreads();
    // stage 2: 3 ch x 32 kz y-lines; Hermitian split from compact slots
    int half = t >> 1;
    bool odd = (t & 1) != 0;
    for (int line = w; line < 96; line += 16) {
        int ch = line >> 5, kz = line & 31;
        const float2* shc = sh + ch*K1CH;
        int a1 = kz;
        int a2 = (kz == 0) ? 0 : (64 - kz);
        float fz2 = (float)(kz*kz);
        float2 v[4];
#pragma unroll
        for (int r = 0; r < 4; r++) {
            int m = half + 16*r;                 // y = t+32r, parity = t&1
            float2 P1 = shc[m*K1SL + a1];
            float2 P2 = shc[m*K1SL + a2];
            if (!odd) v[r] = make_float2(0.5f*(P1.x + P2.x), 0.5f*(P1.y - P2.y));
            else      v[r] = make_float2(0.5f*(P1.y + P2.y), 0.5f*(P2.x - P1.x));
        }
        warp_fft128<0>(v, tw, t);
        float2* dst = d_sp + (((size_t)(b*3 + ch)*NRES + x)*NKZ + kz)*NRES;
#pragma unroll
        for (int r = 0; r < 4; r++) {
            float fy = freq_of(4*u + r);         // freq at address t+32r
            if (fy*fy + fz2 <= CUT2) dst[t + 32*r] = v[r];
        }
    }
}

// ------------- K2: per-line cutoff; sequential fwd X/YZ FFTs + combine + inverse
// 128-thread blocks (4 lines) for fine-grained scheduling / small tail quantum.
__global__ void __launch_bounds__(128, 10) k_specX() {
    extern __shared__ float2 tile[];            // 2 * K2TS float2 (10 KB)
    __shared__ float2 twf[64];
    __shared__ float2 twi[64];
    int tid = threadIdx.x, l = tid >> 5, t = tid & 31;
    build_tw64(twf, tid, -1.f);
    if (tid >= 64 && tid < 128) build_tw64(twi, tid - 64, 1.f);
    int c = blockIdx.x, kz = blockIdx.y, b = blockIdx.z;
    int kya0 = K2L*c;
    const float TWOPI = 6.28318530717958647f;
    float fz = (float)kz;
    float fz2 = fz*fz;
    float2* tileX  = tile;
    float2* tileYZ = tile + K2TS;
    {
        const float2* src0 = d_sp + ((size_t)(b*3 + 0)*NRES*NKZ + kz)*NRES + kya0;
        const float2* src1 = src0 + (size_t)NRES*NKZ*NRES;
        const float2* src2 = src1 + (size_t)NRES*NKZ*NRES;
        for (int i = tid; i < 128*K2L; i += 128) {
            int xx = i >> 2, kyl = i & 3;
            int kya = kya0 + kyl;
            float fy = freq_of(4*bitrev5(kya & 31) + (kya >> 5));
            if (fy*fy + fz2 > CUT2) continue;          // cut line: no load
            size_t off = (size_t)xx*NKZ*NRES + kyl;
            float2 e1 = src1[off];
            float2 e2 = src2[off];
            tileX[xx*K2P + kyl] = src0[off];
            tileYZ[xx*K2P + kyl] = make_float2(TWOPI*(fy*e1.x + fz*e2.x),
                                               TWOPI*(fy*e1.y + fz*e2.y));
        }
    }
    __syncthreads();
    int kya = kya0 + l;
    int fyi = 4*bitrev5(kya & 31) + (kya >> 5);
    float fy = freq_of(fyi);
    int u = bitrev5(t);
    if (fy*fy + fz2 <= CUT2) {
        {
            float2 vX[4];
#pragma unroll
            for (int r = 0; r < 4; r++) vX[r] = tileX[(t + 32*r)*K2P + l];
            warp_fft128<0>(vX, twf, t);
#pragma unroll
            for (int r = 0; r < 4; r++) tileX[(t + 32*r)*K2P + l] = vX[r];
        }
        float2 v[4];
#pragma unroll
        for (int r = 0; r < 4; r++) v[r] = tileYZ[(t + 32*r)*K2P + l];
        warp_fft128<0>(v, twf, t);
#pragma unroll
        for (int r = 0; r < 4; r++) {
            float2 xs = tileX[(t + 32*r)*K2P + l];
            int kx = 4*u + r;
            float fx = (float)(kx < 64 ? kx : kx - 128);
            float wx = TWOPI * fx;
            float2 acc = make_float2(wx*xs.x + v[r].x, wx*xs.y + v[r].y);
            float d2 = fx*fx + fy*fy + fz2;
            float G = expf(-0.01220703125f * d2);            // 0.5*(sig*2/128)^2
            float L = -39.478417604357434f * d2 + 1e-6f;     // -4*pi^2*|f|^2 + eps
            v[r] = make_float2(G*acc.y/L, -G*acc.x/L);       // -i*G*acc/L
            if (kx == 0 && fyi == 0 && kz == 0) v[r] = make_float2(0.f, 0.f);
        }
        warp_ifft128_rev(v, twi, t);            // -> natural x order
#pragma unroll
        for (int r = 0; r < 4; r++) tileX[(t + 32*r)*K2P + l] = v[r];
    }
    __syncthreads();
    float2* dst = d_inv1 + (size_t)(b*NKZ + kz)*NRES*NRES + kya0;
    for (int i = tid; i < 128*K2L; i += 128) {
        int xx = i >> 2, kyl = i & 3;
        int kya2 = kya0 + kyl;
        float fyw = freq_of(4*bitrev5(kya2 & 31) + (kya2 >> 5));
        if (fyw*fyw + fz2 > CUT2) continue;
        dst[(size_t)xx*NRES + kyl] = tileX[xx*K2P + kyl];
    }
}

// --------------- K3: inverse y-FFT (mirror-DIT) + packed-pair C2R z-FFTs
// Compact smem: only kz<32 columns (rest identically zero).
__global__ void __launch_bounds__(512, 3) k_invYZ() {
    extern __shared__ float2 sh[];              // 128 * K3ST float2 (~34 KB)
    __shared__ float2 twi[64];
    int tid = threadIdx.x, w = tid >> 5, t = tid & 31;
    build_tw64(twi, tid, 1.f);
    __syncthreads();
    int x = blockIdx.x, b = blockIdx.y;
    int u = bitrev5(t);
    // stage 1: ky-lines for kz<32 only (2 iterations per warp)
    for (int kz = w; kz < KZCUT; kz += 16) {
        float fz2 = (float)(kz*kz);
        const float2* in = d_inv1 + ((size_t)(b*NKZ + kz)*NRES + x)*NRES;
        float2 v[4];
#pragma unroll
        for (int r = 0; r < 4; r++) {
            float fy = freq_of(4*u + r);         // freq at address t+32r
            v[r] = (fy*fy + fz2 <= CUT2) ? in[t + 32*r] : make_float2(0.f, 0.f);
        }
        warp_ifft128_rev(v, twi, t);            // natural y = t+32r
#pragma unroll
        for (int r = 0; r < 4; r++) sh[(t + 32*r)*K3ST + kz] = v[r];
    }
    __syncthreads();
    // stage 2: 64 packed C2R pairs. Spectrum zero for kz in [32,64]:
    //   v[0] = combine(row[t]); v[1] = v[2] = 0; v[3] = conj-combine(row[32-t]).
    const float sc = 1.0f / 2097152.0f;         // 1/128^3
    float* outb = d_phi + (size_t)(b*NRES + x) * NRES * NRES;
    for (int j = 0; j < 4; j++) {
        int m = w + 16*j;
        const float2* rowA = sh + (2*m)*K3ST;
        const float2* rowB = rowA + K3ST;
        float2 v[4];
        {
            float2 A = rowA[t], B = rowB[t];
            v[0] = make_float2(A.x - B.y, A.y + B.x);
        }
        v[1] = make_float2(0.f, 0.f);
        v[2] = make_float2(0.f, 0.f);
        if (t == 0) v[3] = make_float2(0.f, 0.f);
        else {
            float2 A = rowA[32 - t], B = rowB[32 - t];
            v[3] = make_float2(A.x + B.y, B.x - A.y);
        }
        warp_fft128<1>(v, twi, t);              // v[r] = phi(4*bitrev5(t)+r)
        float4* oA4 = (float4*)(outb + (2*m)*NRES);
        float4* oB4 = (float4*)(outb + (2*m+1)*NRES);
        oA4[t] = make_float4(v[0].x*sc, v[1].x*sc, v[2].x*sc, v[3].x*sc);
        oB4[t] = make_float4(v[0].y*sc, v[1].y*sc, v[2].y*sc, v[3].y*sc);
    }
}

// ---------------------------------------------------------------- gather + mean
__global__ void k_gather(const float* __restrict__ V) {
    __shared__ float red[256];
    int id = blockIdx.x * 256 + threadIdx.x;    // 131072; b uniform per block
    int b = id >> 16;
    float px = V[3*id+0]*128.f, py = V[3*id+1]*128.f, pz = V[3*id+2]*128.f;
    int ix0 = max(0, min(127, (int)floorf(px)));
    int iy0 = max(0, min(127, (int)floorf(py)));
    int iz0 = max(0, min(127, (int)floorf(pz)));
    float fx = px - (float)ix0, fy = py - (float)iy0, fz = pz - (float)iz0;
    int ix[2] = {ix0, (ix0+1)&127};
    int iy[2] = {iy0, (iy0+1)&127};
    int az[2] = {pphi(iz0), pphi((iz0+1)&127)};
    float wx[2] = {1.f-fx, fx}, wy[2] = {1.f-fy, fy}, wz[2] = {1.f-fz, fz};
    const float* ph = d_phi + (size_t)b*VOL;
    float fv = 0.f;
#pragma unroll
    for (int cx = 0; cx < 2; cx++)
#pragma unroll
        for (int cy = 0; cy < 2; cy++)
#pragma unroll
            for (int cz = 0; cz < 2; cz++)
                fv += wx[cx]*wy[cy]*wz[cz] * ph[(ix[cx]*NRES + iy[cy])*NRES + az[cz]];
    red[threadIdx.x] = fv;
    __syncthreads();
    for (int s = 128; s > 0; s >>= 1) {
        if (threadIdx.x < s) red[threadIdx.x] += red[threadIdx.x + s];
        __syncthreads();
    }
    if (threadIdx.x == 0) atomicAdd(&d_accum[b], red[0]);
}

// ---------------------------------------------------------------- finalize
__global__ void k_final(float* __restrict__ out) {
    int gw = blockIdx.x * 8 + (threadIdx.x >> 5);    // 32768 rows
    int t = threadIdx.x & 31;
    int b = gw >> 14;
    float off  = d_accum[b] * (1.0f/65536.0f);
    float p000 = d_phi[(size_t)b * VOL];             // pphi(0)=0
    float s = 0.5f / fabsf(p000 - off);
    const float4* in4 = (const float4*)(d_phi + (size_t)gw * NRES);
    float4 v = in4[t];                               // z = 4*bitrev5(t)+r
    float4 o;
    o.x = -(v.x - off) * s;
    o.y = -(v.y - off) * s;
    o.z = -(v.z - off) * s;
    o.w = -(v.w - off) * s;
    float4* out4 = (float4*)(out + (size_t)gw * NRES);
    out4[bitrev5(t)] = o;
}

// ---------------------------------------------------------------- launch
extern "C" void kernel_launch(void* const* d_in, const int* in_sizes, int n_in,
                              void* d_out, int out_size) {
    const float* V = (const float*)d_in[0];
    const float* N = (const float*)d_in[1];
    float* out = (float*)d_out;

    const int k1Bytes = 3*K1CH*sizeof(float2);        // 99840
    const int k3Bytes = 128*K3ST*sizeof(float2);      // 33792
    const int k2Bytes = 2*K2TS*sizeof(float2);        // 10240
    cudaFuncSetAttribute(k_fwdZY, cudaFuncAttributeMaxDynamicSharedMemorySize, k1Bytes);
    cudaFuncSetAttribute(k_invYZ, cudaFuncAttributeMaxDynamicSharedMemorySize, k3Bytes);

    k_zero<<<4096, 256>>>();
    k_scatter<<<512, 256>>>(V, N);
    k_fwdZY<<<dim3(128, 2), 512, k1Bytes>>>();        // 256 (b,x) slabs, 3 ch each
    k_specX<<<dim3(32, KZCUT, 2), 128, k2Bytes>>>();  // 2048 fine-grained blocks
    k_invYZ<<<dim3(128, 2), 512, k3Bytes>>>();        // 256 planes
    k_gather<<<512, 256>>>(V);
    k_final<<<4096, 256>>>(out);
}